// round 5
// baseline (speedup 1.0000x reference)
#include <cuda_runtime.h>

#define Bsz  4
#define Mtok 2048
#define Dh   1024
#define NE   64
#define PS   32
#define NP   2048            // NE*PS
#define BM   (Bsz*Mtok)      // 8192

// ---------------- scratch (device globals; no allocations allowed) --------
__device__ float g_logits  [(size_t)Bsz * Mtok * NP];  // 64 MB
__device__ float g_dispatch[(size_t)Bsz * Mtok * NP];  // 64 MB
__device__ float g_combine [(size_t)Bsz * Mtok * NP];  // 64 MB
__device__ float g_slots   [(size_t)Bsz * NP * Dh];    // 32 MB
__device__ float g_y       [(size_t)Bsz * NP * Dh];    // 32 MB

// ---------------- NN SGEMM: C[Mr x Nc] = A[Mr x K] * B[K x Nc] -----------
// 64x64 tile, TK=16, 256 threads, 4x4 per-thread microtile. Batched via z.
__global__ __launch_bounds__(256) void sgemm_nn(
    const float* __restrict__ A, const float* __restrict__ Bm,
    float* __restrict__ C, int Nc, int K,
    long long sA, long long sB, long long sC)
{
    __shared__ float As[16][68];
    __shared__ float Bs[16][68];

    const float* Ab = A  + (size_t)blockIdx.z * sA;
    const float* Bb = Bm + (size_t)blockIdx.z * sB;
    float*       Cb = C  + (size_t)blockIdx.z * sC;

    const int tid = threadIdx.x;
    const int tx = tid & 15, ty = tid >> 4;
    const int row0 = blockIdx.y * 64;
    const int col0 = blockIdx.x * 64;

    const int lam = tid >> 2;          // 0..63 (A row within tile)
    const int lak = (tid & 3) << 2;    // 0,4,8,12
    const int lbk = tid >> 4;          // 0..15
    const int lbn = (tid & 15) << 2;   // 0..60

    float acc[4][4] = {};

    for (int k0 = 0; k0 < K; k0 += 16) {
        float4 av = *(const float4*)&Ab[(size_t)(row0 + lam) * K + k0 + lak];
        *(float4*)&Bs[lbk][lbn] =
            *(const float4*)&Bb[(size_t)(k0 + lbk) * Nc + col0 + lbn];
        As[lak + 0][lam] = av.x;
        As[lak + 1][lam] = av.y;
        As[lak + 2][lam] = av.z;
        As[lak + 3][lam] = av.w;
        __syncthreads();

#pragma unroll
        for (int kk = 0; kk < 16; kk++) {
            float4 a = *(const float4*)&As[kk][ty << 2];
            float4 b = *(const float4*)&Bs[kk][tx << 2];
            float ar[4] = {a.x, a.y, a.z, a.w};
            float br[4] = {b.x, b.y, b.z, b.w};
#pragma unroll
            for (int i = 0; i < 4; i++)
#pragma unroll
                for (int j = 0; j < 4; j++)
                    acc[i][j] = fmaf(ar[i], br[j], acc[i][j]);
        }
        __syncthreads();
    }

#pragma unroll
    for (int i = 0; i < 4; i++) {
        float4 v = make_float4(acc[i][0], acc[i][1], acc[i][2], acc[i][3]);
        *(float4*)&Cb[(size_t)(row0 + (ty << 2) + i) * Nc + col0 + (tx << 2)] = v;
    }
}

// ---------------- TN SGEMM: C[I x J] = sum_k A[k][i] * B[k][j] ------------
// A: K x I row-major, B: K x J row-major. Batched via z.
__global__ __launch_bounds__(256) void sgemm_tn(
    const float* __restrict__ A, const float* __restrict__ Bm,
    float* __restrict__ C, int I, int J, int K,
    long long sA, long long sB, long long sC)
{
    __shared__ float As[16][68];
    __shared__ float Bs[16][68];

    const float* Ab = A  + (size_t)blockIdx.z * sA;
    const float* Bb = Bm + (size_t)blockIdx.z * sB;
    float*       Cb = C  + (size_t)blockIdx.z * sC;

    const int tid = threadIdx.x;
    const int tx = tid & 15, ty = tid >> 4;
    const int i0 = blockIdx.y * 64;
    const int j0 = blockIdx.x * 64;

    const int lk = tid >> 4;           // 0..15
    const int lv = (tid & 15) << 2;    // 0..60

    float acc[4][4] = {};

    for (int k0 = 0; k0 < K; k0 += 16) {
        *(float4*)&As[lk][lv] =
            *(const float4*)&Ab[(size_t)(k0 + lk) * I + i0 + lv];
        *(float4*)&Bs[lk][lv] =
            *(const float4*)&Bb[(size_t)(k0 + lk) * J + j0 + lv];
        __syncthreads();

#pragma unroll
        for (int kk = 0; kk < 16; kk++) {
            float4 a = *(const float4*)&As[kk][ty << 2];
            float4 b = *(const float4*)&Bs[kk][tx << 2];
            float ar[4] = {a.x, a.y, a.z, a.w};
            float br[4] = {b.x, b.y, b.z, b.w};
#pragma unroll
            for (int i = 0; i < 4; i++)
#pragma unroll
                for (int j = 0; j < 4; j++)
                    acc[i][j] = fmaf(ar[i], br[j], acc[i][j]);
        }
        __syncthreads();
    }

#pragma unroll
    for (int i = 0; i < 4; i++) {
        float4 v = make_float4(acc[i][0], acc[i][1], acc[i][2], acc[i][3]);
        *(float4*)&Cb[(size_t)(i0 + (ty << 2) + i) * J + j0 + (tx << 2)] = v;
    }
}

// ---------------- expert GEMM: y[b,n,p,:] = slots[b,n,p,:] @ W[n] + bias[n]
// Per block: 32 x 64 output tile. grid = (Dh/64, Bsz, NE).
__global__ __launch_bounds__(256) void expert_gemm(
    const float* __restrict__ slots, const float* __restrict__ W,
    const float* __restrict__ bias, float* __restrict__ y)
{
    const int n = blockIdx.z, b = blockIdx.y;
    const int e0 = blockIdx.x * 64;

    const float* A  = slots + ((size_t)b * NP + (size_t)n * PS) * Dh;  // 32 x Dh
    const float* Bw = W + (size_t)n * Dh * Dh;                         // Dh x Dh
    float*       Cp = y + ((size_t)b * NP + (size_t)n * PS) * Dh;

    __shared__ float As[16][36];
    __shared__ float Bs[16][68];

    const int tid = threadIdx.x;
    const int tx = tid & 15, ty = tid >> 4;

    const int lam = tid >> 3;          // 0..31
    const int lak = (tid & 7) << 1;    // 0..14 step 2
    const int lbk = tid >> 4;          // 0..15
    const int lbn = (tid & 15) << 2;   // 0..60

    float acc[2][4] = {};

    for (int k0 = 0; k0 < Dh; k0 += 16) {
        float2 av = *(const float2*)&A[(size_t)lam * Dh + k0 + lak];
        *(float4*)&Bs[lbk][lbn] =
            *(const float4*)&Bw[(size_t)(k0 + lbk) * Dh + e0 + lbn];
        As[lak + 0][lam] = av.x;
        As[lak + 1][lam] = av.y;
        __syncthreads();

#pragma unroll
        for (int kk = 0; kk < 16; kk++) {
            float a0 = As[kk][(ty << 1) + 0];
            float a1 = As[kk][(ty << 1) + 1];
            float4 bv = *(const float4*)&Bs[kk][tx << 2];
            float br[4] = {bv.x, bv.y, bv.z, bv.w};
#pragma unroll
            for (int j = 0; j < 4; j++) {
                acc[0][j] = fmaf(a0, br[j], acc[0][j]);
                acc[1][j] = fmaf(a1, br[j], acc[1][j]);
            }
        }
        __syncthreads();
    }

    float4 bb = *(const float4*)&bias[(size_t)n * Dh + e0 + (tx << 2)];
    float bias_r[4] = {bb.x, bb.y, bb.z, bb.w};
#pragma unroll
    for (int i = 0; i < 2; i++) {
        float4 v = make_float4(acc[i][0] + bias_r[0], acc[i][1] + bias_r[1],
                               acc[i][2] + bias_r[2], acc[i][3] + bias_r[3]);
        *(float4*)&Cp[(size_t)((ty << 1) + i) * Dh + e0 + (tx << 2)] = v;
    }
}

// ---------------- dispatch softmax: softmax over batch axis (4 values) ----
__global__ __launch_bounds__(256) void dispatch_softmax(
    const float* __restrict__ logits, float* __restrict__ disp)
{
    const size_t S = (size_t)Mtok * NP;
    size_t idx = (size_t)blockIdx.x * blockDim.x + threadIdx.x;  // over Mtok*NP
    float v0 = logits[idx];
    float v1 = logits[idx + S];
    float v2 = logits[idx + 2 * S];
    float v3 = logits[idx + 3 * S];
    float mx = fmaxf(fmaxf(v0, v1), fmaxf(v2, v3));
    float e0 = __expf(v0 - mx), e1 = __expf(v1 - mx);
    float e2 = __expf(v2 - mx), e3 = __expf(v3 - mx);
    float inv = 1.0f / (e0 + e1 + e2 + e3);
    disp[idx]         = e0 * inv;
    disp[idx + S]     = e1 * inv;
    disp[idx + 2 * S] = e2 * inv;
    disp[idx + 3 * S] = e3 * inv;
}

// ---------------- combine softmax: row softmax over NP=2048 slots ---------
__device__ __forceinline__ float warpMax(float v) {
#pragma unroll
    for (int o = 16; o > 0; o >>= 1) v = fmaxf(v, __shfl_xor_sync(0xffffffffu, v, o));
    return v;
}
__device__ __forceinline__ float warpSum(float v) {
#pragma unroll
    for (int o = 16; o > 0; o >>= 1) v += __shfl_xor_sync(0xffffffffu, v, o);
    return v;
}

__global__ __launch_bounds__(256) void combine_softmax(
    const float* __restrict__ logits, float* __restrict__ comb)
{
    const int row = blockIdx.x;                     // 0..BM-1
    const float* rp = logits + (size_t)row * NP;
    float*       wp = comb   + (size_t)row * NP;
    const int t = threadIdx.x;
    const int lane = t & 31, wid = t >> 5;

    float v[8];
    float mx = -1e30f;
#pragma unroll
    for (int i = 0; i < 8; i++) {
        v[i] = rp[t + i * 256];
        mx = fmaxf(mx, v[i]);
    }

    __shared__ float red[8];
    mx = warpMax(mx);
    if (lane == 0) red[wid] = mx;
    __syncthreads();
    mx = red[0];
#pragma unroll
    for (int i = 1; i < 8; i++) mx = fmaxf(mx, red[i]);
    __syncthreads();

    float s = 0.0f;
#pragma unroll
    for (int i = 0; i < 8; i++) {
        v[i] = __expf(v[i] - mx);
        s += v[i];
    }
    s = warpSum(s);
    if (lane == 0) red[wid] = s;
    __syncthreads();
    float tot = 0.0f;
#pragma unroll
    for (int i = 0; i < 8; i++) tot += red[i];
    float inv = 1.0f / tot;

#pragma unroll
    for (int i = 0; i < 8; i++) wp[t + i * 256] = v[i] * inv;
}

// ---------------- launch --------------------------------------------------
extern "C" void kernel_launch(void* const* d_in, const int* in_sizes, int n_in,
                              void* d_out, int out_size)
{
    const float* x    = (const float*)d_in[0];  // (B, M, D)
    const float* phi  = (const float*)d_in[1];  // (D, N, P) = (D, NP)
    const float* W    = (const float*)d_in[2];  // (N, D, D)
    const float* bias = (const float*)d_in[3];  // (N, D)
    float* out = (float*)d_out;                 // (B, M, D)

    float *logits, *disp, *comb, *slots, *y;
    cudaGetSymbolAddress((void**)&logits, g_logits);
    cudaGetSymbolAddress((void**)&disp,   g_dispatch);
    cudaGetSymbolAddress((void**)&comb,   g_combine);
    cudaGetSymbolAddress((void**)&slots,  g_slots);
    cudaGetSymbolAddress((void**)&y,      g_y);

    // 1) logits = x @ phi : (BM x Dh) * (Dh x NP)
    sgemm_nn<<<dim3(NP / 64, BM / 64, 1), 256>>>(
        x, phi, logits, NP, Dh, 0, 0, 0);

    // 2) dispatch = softmax over batch axis
    dispatch_softmax<<<(Mtok * NP) / 256, 256>>>(logits, disp);

    // 3) combine = softmax over NP slots per (b, m)
    combine_softmax<<<BM, 256>>>(logits, comb);

    // 4) slots[b] = dispatch[b]^T @ x[b] : (NP x Mtok)^T-layout * (Mtok x Dh)
    sgemm_tn<<<dim3(Dh / 64, NP / 64, Bsz), 256>>>(
        disp, x, slots, NP, Dh, Mtok,
        (long long)Mtok * NP, (long long)Mtok * Dh, (long long)NP * Dh);

    // 5) y[b,n] = slots[b,n] @ W[n] + bias[n]
    expert_gemm<<<dim3(Dh / 64, Bsz, NE), 256>>>(slots, W, bias, y);

    // 6) out[b] = combine[b] @ y[b] : (Mtok x NP) * (NP x Dh)
    sgemm_nn<<<dim3(Dh / 64, Mtok / 64, Bsz), 256>>>(
        comb, y, out, Dh, NP,
        (long long)Mtok * NP, (long long)NP * Dh, (long long)Mtok * Dh);
}

// round 7
// speedup vs baseline: 1.1361x; 1.1361x over previous
#include <cuda_runtime.h>

#define Bsz  4
#define Mtok 2048
#define Dh   1024
#define NE   64
#define PS   32
#define NP   2048            // NE*PS
#define BM   (Bsz*Mtok)      // 8192

// ---------------- scratch (device globals; no allocations allowed) --------
__device__ float g_logits  [(size_t)Bsz * Mtok * NP];  // 64 MB
__device__ float g_dispatch[(size_t)Bsz * Mtok * NP];  // 64 MB
__device__ float g_combine [(size_t)Bsz * Mtok * NP];  // 64 MB
__device__ float g_slots   [(size_t)Bsz * NP * Dh];    // 32 MB
__device__ float g_y       [(size_t)Bsz * NP * Dh];    // 32 MB

// ---------------- shared compute: 128x128 tile, 8x8 microtile -------------
__device__ __forceinline__ void mt_compute(
    const float (*As)[132], const float (*Bs)[132],
    int wm, int wn, int lm, int ln, float acc[8][8])
{
#pragma unroll
    for (int kk = 0; kk < 16; kk++) {
        float4 a0 = *(const float4*)&As[kk][wm + lm];
        float4 a1 = *(const float4*)&As[kk][wm + lm + 4];
        float4 b0 = *(const float4*)&Bs[kk][wn + ln];
        float4 b1 = *(const float4*)&Bs[kk][wn + ln + 4];
        float ar[8] = {a0.x, a0.y, a0.z, a0.w, a1.x, a1.y, a1.z, a1.w};
        float br[8] = {b0.x, b0.y, b0.z, b0.w, b1.x, b1.y, b1.z, b1.w};
#pragma unroll
        for (int i = 0; i < 8; i++)
#pragma unroll
            for (int j = 0; j < 8; j++)
                acc[i][j] = fmaf(ar[i], br[j], acc[i][j]);
    }
}

// ---------------- NN SGEMM: C[M x N] = A[M x K] * B[K x N], 128x128 tiles -
__global__ __launch_bounds__(256, 2) void sgemm_nn128(
    const float* __restrict__ A, const float* __restrict__ Bm,
    float* __restrict__ C, int Nld, int K,
    long long sA, long long sB, long long sC)
{
    __shared__ float As[2][16][132];
    __shared__ float Bs[2][16][132];

    const float* Ab = A  + (size_t)blockIdx.z * sA;
    const float* Bb = Bm + (size_t)blockIdx.z * sB;
    float*       Cb = C  + (size_t)blockIdx.z * sC;

    const int tid  = threadIdx.x;
    const int row0 = blockIdx.y * 128;
    const int col0 = blockIdx.x * 128;

    // A loader: thread -> row = tid>>1 (0..127), k-base = (tid&1)*8
    const int arow = tid >> 1;
    const int akb  = (tid & 1) * 8;
    const float* aP = Ab + (size_t)(row0 + arow) * K + akb;

    // B loader: thread -> k-row = tid>>4 (0..15), n-base = (tid&15)*8
    const int bkr = tid >> 4;
    const int bnc = (tid & 15) * 8;
    const float* bP = Bb + (size_t)bkr * Nld + col0 + bnc;

    const int wid = tid >> 5, lane = tid & 31;
    const int wm = (wid >> 1) * 32, wn = (wid & 1) * 64;
    const int lm = (lane >> 3) * 8, ln = (lane & 7) * 8;

    float acc[8][8] = {};
    float4 aR0, aR1, bR0, bR1;

    // preload tile 0
    aR0 = *(const float4*)(aP);
    aR1 = *(const float4*)(aP + 4);
    bR0 = *(const float4*)(bP);
    bR1 = *(const float4*)(bP + 4);
    {
        float* as = &As[0][akb][arow];
        as[0*132] = aR0.x; as[1*132] = aR0.y; as[2*132] = aR0.z; as[3*132] = aR0.w;
        as[4*132] = aR1.x; as[5*132] = aR1.y; as[6*132] = aR1.z; as[7*132] = aR1.w;
        *(float4*)&Bs[0][bkr][bnc]     = bR0;
        *(float4*)&Bs[0][bkr][bnc + 4] = bR1;
    }
    __syncthreads();

    const int nT = K / 16;
    for (int t = 0; t < nT; t++) {
        const int cur = t & 1;
        if (t + 1 < nT) {
            aR0 = *(const float4*)(aP + (size_t)(t + 1) * 16);
            aR1 = *(const float4*)(aP + (size_t)(t + 1) * 16 + 4);
            bR0 = *(const float4*)(bP + (size_t)(t + 1) * 16 * Nld);
            bR1 = *(const float4*)(bP + (size_t)(t + 1) * 16 * Nld + 4);
        }
        mt_compute(As[cur], Bs[cur], wm, wn, lm, ln, acc);
        if (t + 1 < nT) {
            const int nxt = cur ^ 1;
            float* as = &As[nxt][akb][arow];
            as[0*132] = aR0.x; as[1*132] = aR0.y; as[2*132] = aR0.z; as[3*132] = aR0.w;
            as[4*132] = aR1.x; as[5*132] = aR1.y; as[6*132] = aR1.z; as[7*132] = aR1.w;
            *(float4*)&Bs[nxt][bkr][bnc]     = bR0;
            *(float4*)&Bs[nxt][bkr][bnc + 4] = bR1;
            __syncthreads();
        }
    }

#pragma unroll
    for (int i = 0; i < 8; i++) {
        float* cp = &Cb[(size_t)(row0 + wm + lm + i) * Nld + col0 + wn + ln];
        *(float4*)cp       = make_float4(acc[i][0], acc[i][1], acc[i][2], acc[i][3]);
        *(float4*)(cp + 4) = make_float4(acc[i][4], acc[i][5], acc[i][6], acc[i][7]);
    }
}

// ---------------- TN SGEMM: C[I x J] = sum_k A[k][i] * B[k][j] ------------
__global__ __launch_bounds__(256, 2) void sgemm_tn128(
    const float* __restrict__ A, const float* __restrict__ Bm,
    float* __restrict__ C, int I, int J, int K,
    long long sA, long long sB, long long sC)
{
    __shared__ float As[2][16][132];
    __shared__ float Bs[2][16][132];

    const float* Ab = A  + (size_t)blockIdx.z * sA;
    const float* Bb = Bm + (size_t)blockIdx.z * sB;
    float*       Cb = C  + (size_t)blockIdx.z * sC;

    const int tid = threadIdx.x;
    const int i0 = blockIdx.y * 128;
    const int j0 = blockIdx.x * 128;

    const int kr = tid >> 4;          // 0..15
    const int vc = (tid & 15) * 8;    // 0..120
    const float* aP = Ab + (size_t)kr * I + i0 + vc;
    const float* bP = Bb + (size_t)kr * J + j0 + vc;

    const int wid = tid >> 5, lane = tid & 31;
    const int wm = (wid >> 1) * 32, wn = (wid & 1) * 64;
    const int lm = (lane >> 3) * 8, ln = (lane & 7) * 8;

    float acc[8][8] = {};
    float4 aR0, aR1, bR0, bR1;

    aR0 = *(const float4*)(aP);
    aR1 = *(const float4*)(aP + 4);
    bR0 = *(const float4*)(bP);
    bR1 = *(const float4*)(bP + 4);
    *(float4*)&As[0][kr][vc]     = aR0;
    *(float4*)&As[0][kr][vc + 4] = aR1;
    *(float4*)&Bs[0][kr][vc]     = bR0;
    *(float4*)&Bs[0][kr][vc + 4] = bR1;
    __syncthreads();

    const int nT = K / 16;
    for (int t = 0; t < nT; t++) {
        const int cur = t & 1;
        if (t + 1 < nT) {
            aR0 = *(const float4*)(aP + (size_t)(t + 1) * 16 * I);
            aR1 = *(const float4*)(aP + (size_t)(t + 1) * 16 * I + 4);
            bR0 = *(const float4*)(bP + (size_t)(t + 1) * 16 * J);
            bR1 = *(const float4*)(bP + (size_t)(t + 1) * 16 * J + 4);
        }
        mt_compute(As[cur], Bs[cur], wm, wn, lm, ln, acc);
        if (t + 1 < nT) {
            const int nxt = cur ^ 1;
            *(float4*)&As[nxt][kr][vc]     = aR0;
            *(float4*)&As[nxt][kr][vc + 4] = aR1;
            *(float4*)&Bs[nxt][kr][vc]     = bR0;
            *(float4*)&Bs[nxt][kr][vc + 4] = bR1;
            __syncthreads();
        }
    }

#pragma unroll
    for (int i = 0; i < 8; i++) {
        float* cp = &Cb[(size_t)(i0 + wm + lm + i) * J + j0 + wn + ln];
        *(float4*)cp       = make_float4(acc[i][0], acc[i][1], acc[i][2], acc[i][3]);
        *(float4*)(cp + 4) = make_float4(acc[i][4], acc[i][5], acc[i][6], acc[i][7]);
    }
}

// ---------------- expert GEMM (regrouped): 128 rows (4b x 32p) per expert -
// grid = (Dh/128, NE). Row r in tile: b = r>>5, p = r&31.
__global__ __launch_bounds__(256, 2) void expert_gemm128(
    const float* __restrict__ slots, const float* __restrict__ W,
    const float* __restrict__ bias, float* __restrict__ y)
{
    __shared__ float As[2][16][132];
    __shared__ float Bs[2][16][132];

    const int n  = blockIdx.y;
    const int e0 = blockIdx.x * 128;

    const float* Bw = W + (size_t)n * Dh * Dh;

    const int tid = threadIdx.x;

    // A loader: row = tid>>1 within the 128 gathered rows
    const int arow = tid >> 1;
    const int akb  = (tid & 1) * 8;
    const int ab   = arow >> 5, ap = arow & 31;
    const float* aP = slots + ((size_t)ab * NP + (size_t)n * PS + ap) * Dh + akb;

    const int bkr = tid >> 4;
    const int bnc = (tid & 15) * 8;
    const float* bP = Bw + (size_t)bkr * Dh + e0 + bnc;

    const int wid = tid >> 5, lane = tid & 31;
    const int wm = (wid >> 1) * 32, wn = (wid & 1) * 64;
    const int lm = (lane >> 3) * 8, ln = (lane & 7) * 8;

    float acc[8][8] = {};
    float4 aR0, aR1, bR0, bR1;

    aR0 = *(const float4*)(aP);
    aR1 = *(const float4*)(aP + 4);
    bR0 = *(const float4*)(bP);
    bR1 = *(const float4*)(bP + 4);
    {
        float* as = &As[0][akb][arow];
        as[0*132] = aR0.x; as[1*132] = aR0.y; as[2*132] = aR0.z; as[3*132] = aR0.w;
        as[4*132] = aR1.x; as[5*132] = aR1.y; as[6*132] = aR1.z; as[7*132] = aR1.w;
        *(float4*)&Bs[0][bkr][bnc]     = bR0;
        *(float4*)&Bs[0][bkr][bnc + 4] = bR1;
    }
    __syncthreads();

    const int nT = Dh / 16;
    for (int t = 0; t < nT; t++) {
        const int cur = t & 1;
        if (t + 1 < nT) {
            aR0 = *(const float4*)(aP + (size_t)(t + 1) * 16);
            aR1 = *(const float4*)(aP + (size_t)(t + 1) * 16 + 4);
            bR0 = *(const float4*)(bP + (size_t)(t + 1) * 16 * Dh);
            bR1 = *(const float4*)(bP + (size_t)(t + 1) * 16 * Dh + 4);
        }
        mt_compute(As[cur], Bs[cur], wm, wn, lm, ln, acc);
        if (t + 1 < nT) {
            const int nxt = cur ^ 1;
            float* as = &As[nxt][akb][arow];
            as[0*132] = aR0.x; as[1*132] = aR0.y; as[2*132] = aR0.z; as[3*132] = aR0.w;
            as[4*132] = aR1.x; as[5*132] = aR1.y; as[6*132] = aR1.z; as[7*132] = aR1.w;
            *(float4*)&Bs[nxt][bkr][bnc]     = bR0;
            *(float4*)&Bs[nxt][bkr][bnc + 4] = bR1;
            __syncthreads();
        }
    }

    float4 bb0 = *(const float4*)&bias[(size_t)n * Dh + e0 + wn + ln];
    float4 bb1 = *(const float4*)&bias[(size_t)n * Dh + e0 + wn + ln + 4];
#pragma unroll
    for (int i = 0; i < 8; i++) {
        const int r = wm + lm + i;
        const int rb = r >> 5, rp = r & 31;
        float* cp = y + ((size_t)rb * NP + (size_t)n * PS + rp) * Dh + e0 + wn + ln;
        *(float4*)cp = make_float4(acc[i][0] + bb0.x, acc[i][1] + bb0.y,
                                   acc[i][2] + bb0.z, acc[i][3] + bb0.w);
        *(float4*)(cp + 4) = make_float4(acc[i][4] + bb1.x, acc[i][5] + bb1.y,
                                         acc[i][6] + bb1.z, acc[i][7] + bb1.w);
    }
}

// ---------------- dispatch softmax: softmax over batch axis (4 values) ----
__global__ __launch_bounds__(256) void dispatch_softmax(
    const float* __restrict__ logits, float* __restrict__ disp)
{
    const size_t S = (size_t)Mtok * NP;
    size_t idx = (size_t)blockIdx.x * blockDim.x + threadIdx.x;
    float v0 = logits[idx];
    float v1 = logits[idx + S];
    float v2 = logits[idx + 2 * S];
    float v3 = logits[idx + 3 * S];
    float mx = fmaxf(fmaxf(v0, v1), fmaxf(v2, v3));
    float e0 = __expf(v0 - mx), e1 = __expf(v1 - mx);
    float e2 = __expf(v2 - mx), e3 = __expf(v3 - mx);
    float inv = 1.0f / (e0 + e1 + e2 + e3);
    disp[idx]         = e0 * inv;
    disp[idx + S]     = e1 * inv;
    disp[idx + 2 * S] = e2 * inv;
    disp[idx + 3 * S] = e3 * inv;
}

// ---------------- combine softmax: row softmax over NP=2048 slots ---------
__device__ __forceinline__ float warpMax(float v) {
#pragma unroll
    for (int o = 16; o > 0; o >>= 1) v = fmaxf(v, __shfl_xor_sync(0xffffffffu, v, o));
    return v;
}
__device__ __forceinline__ float warpSum(float v) {
#pragma unroll
    for (int o = 16; o > 0; o >>= 1) v += __shfl_xor_sync(0xffffffffu, v, o);
    return v;
}

__global__ __launch_bounds__(256) void combine_softmax(
    const float* __restrict__ logits, float* __restrict__ comb)
{
    const int row = blockIdx.x;
    const float* rp = logits + (size_t)row * NP;
    float*       wp = comb   + (size_t)row * NP;
    const int t = threadIdx.x;
    const int lane = t & 31, wid = t >> 5;

    float v[8];
    float mx = -1e30f;
#pragma unroll
    for (int i = 0; i < 8; i++) {
        v[i] = rp[t + i * 256];
        mx = fmaxf(mx, v[i]);
    }

    __shared__ float red[8];
    mx = warpMax(mx);
    if (lane == 0) red[wid] = mx;
    __syncthreads();
    mx = red[0];
#pragma unroll
    for (int i = 1; i < 8; i++) mx = fmaxf(mx, red[i]);
    __syncthreads();

    float s = 0.0f;
#pragma unroll
    for (int i = 0; i < 8; i++) {
        v[i] = __expf(v[i] - mx);
        s += v[i];
    }
    s = warpSum(s);
    if (lane == 0) red[wid] = s;
    __syncthreads();
    float tot = 0.0f;
#pragma unroll
    for (int i = 0; i < 8; i++) tot += red[i];
    float inv = 1.0f / tot;

#pragma unroll
    for (int i = 0; i < 8; i++) wp[t + i * 256] = v[i] * inv;
}

// ---------------- launch --------------------------------------------------
extern "C" void kernel_launch(void* const* d_in, const int* in_sizes, int n_in,
                              void* d_out, int out_size)
{
    const float* x    = (const float*)d_in[0];  // (B, M, D)
    const float* phi  = (const float*)d_in[1];  // (D, N, P) = (D, NP)
    const float* W    = (const float*)d_in[2];  // (N, D, D)
    const float* bias = (const float*)d_in[3];  // (N, D)
    float* out = (float*)d_out;                 // (B, M, D)

    float *logits, *disp, *comb, *slots, *y;
    cudaGetSymbolAddress((void**)&logits, g_logits);
    cudaGetSymbolAddress((void**)&disp,   g_dispatch);
    cudaGetSymbolAddress((void**)&comb,   g_combine);
    cudaGetSymbolAddress((void**)&slots,  g_slots);
    cudaGetSymbolAddress((void**)&y,      g_y);

    // 1) logits = x @ phi : (BM x Dh) * (Dh x NP)
    sgemm_nn128<<<dim3(NP / 128, BM / 128, 1), 256>>>(
        x, phi, logits, NP, Dh, 0, 0, 0);

    // 2) dispatch = softmax over batch axis
    dispatch_softmax<<<(Mtok * NP) / 256, 256>>>(logits, disp);

    // 3) combine = softmax over NP slots per (b, m)
    combine_softmax<<<BM, 256>>>(logits, comb);

    // 4) slots[b] = dispatch[b]^T @ x[b]
    sgemm_tn128<<<dim3(Dh / 128, NP / 128, Bsz), 256>>>(
        disp, x, slots, NP, Dh, Mtok,
        (long long)Mtok * NP, (long long)Mtok * Dh, (long long)NP * Dh);

    // 5) y[b,n] = slots[b,n] @ W[n] + bias[n]  (4 batches share W[n] per tile)
    expert_gemm128<<<dim3(Dh / 128, NE), 256>>>(slots, W, bias, y);

    // 6) out[b] = combine[b] @ y[b]
    sgemm_nn128<<<dim3(Dh / 128, Mtok / 128, Bsz), 256>>>(
        comb, y, out, Dh, NP,
        (long long)Mtok * NP, (long long)NP * Dh, (long long)Mtok * Dh);
}